// round 11
// baseline (speedup 1.0000x reference)
#include <cuda_runtime.h>

#define NB 8
#define NN 512
#define DD 256
#define DH 64
#define NROWS (NB*NN)   // 4096

#define QKV_BLOCKS 256           // 16 rows per block (kernel 1)
#define GRID1 444

#define ATTN_BLOCKS 512          // 8 q-rows per block (kernel 2)
#define GRID2 592                // 4 CTAs/SM * 148 SMs, single wave

// e passthrough: 16777216 float4 total; 32KB chunks stolen per-warp
#define CHUNK4    2048
#define NCHUNKS   8192

// kernel2 smem: Qs 512 + KsT 8192 + S 4096 + Mj 512 = 13312 floats = 53248 B
#define SMEM_BYTES2 (13312 * 4)

__device__ float g_Q[NROWS*DH];
__device__ float g_K[NROWS*DH];
__device__ float g_V[NROWS*DH];
__device__ int   g_chunk;        // copy work-stealing counter (persists across kernels)
__device__ int   g_done;         // qkv completion counter
__device__ int   g_exit;         // exit counter (replay-safe reset)

// ---------------------------------------------------------------------------
// Kernel 1: blocks [0,256) project 16 rows each of Q/K/V; blocks [256,444)
// work-steal copy chunks until qkv is done, then exit (kernel 2 continues).
// ---------------------------------------------------------------------------
__global__ __launch_bounds__(256) void qkv_copy_kernel(
    const float* __restrict__ x, const int* __restrict__ mask,
    const float* __restrict__ Wq, const float* __restrict__ bq,
    const float* __restrict__ Wk, const float* __restrict__ bk,
    const float* __restrict__ Wv, const float* __restrict__ bv,
    float* __restrict__ out, const float* __restrict__ e)
{
    const int t = threadIdx.x;

    if (blockIdx.x < QKV_BLOCKS) {
        __shared__ float xs[16*DD];
        const int row0 = blockIdx.x * 16;

        const float4* x4 = reinterpret_cast<const float4*>(x + (size_t)row0 * DD);
        float4* xs4 = reinterpret_cast<float4*>(xs);
        #pragma unroll
        for (int i = t; i < 16*DD/4; i += 256) xs4[i] = x4[i];
        __syncthreads();

        const int tx = t & 63;
        const int ty = t >> 6;

        float accq[4], acck[4], accv[4];
        #pragma unroll
        for (int r = 0; r < 4; r++) { accq[r] = 0.f; acck[r] = 0.f; accv[r] = 0.f; }

        for (int k = 0; k < DD; k += 4) {
            float4 xv4[4];
            #pragma unroll
            for (int r = 0; r < 4; r++)
                xv4[r] = *reinterpret_cast<const float4*>(&xs[(ty + r*4)*DD + k]);
            #pragma unroll
            for (int kk = 0; kk < 4; kk++) {
                float wq = Wq[(k+kk)*DH + tx];
                float wk = Wk[(k+kk)*DH + tx];
                float wv = Wv[(k+kk)*DH + tx];
                #pragma unroll
                for (int r = 0; r < 4; r++) {
                    float xv = reinterpret_cast<const float*>(&xv4[r])[kk];
                    accq[r] = fmaf(xv, wq, accq[r]);
                    acck[r] = fmaf(xv, wk, acck[r]);
                    accv[r] = fmaf(xv, wv, accv[r]);
                }
            }
        }

        const float bqv = bq[tx], bkv = bk[tx], bvv = bv[tx];
        #pragma unroll
        for (int r = 0; r < 4; r++) {
            int row = row0 + ty + r*4;
            float m = (float)mask[row];
            g_Q[row*DH + tx] = (accq[r] + bqv) * m;
            g_K[row*DH + tx] = (acck[r] + bkv) * m;
            g_V[row*DH + tx] = (accv[r] + bvv) * m;
        }

        __threadfence();
        __syncthreads();
        if (t == 0) atomicAdd(&g_done, 1);
        return;
    }

    // copy blocks: steal chunks until qkv done (or exhausted)
    {
        const int lane = t & 31;
        const float4* __restrict__ src = reinterpret_cast<const float4*>(e);
        float4* __restrict__ dst = reinterpret_cast<float4*>(out + (size_t)NROWS*DH);
        volatile int* vd = &g_done;

        for (;;) {
            if (*vd >= QKV_BLOCKS) break;

            int c = 0;
            if (lane == 0) c = atomicAdd(&g_chunk, 1);
            c = __shfl_sync(0xffffffffu, c, 0);
            if (c >= NCHUNKS) break;

            const size_t base = (size_t)c * CHUNK4 + lane;
            #pragma unroll 1
            for (int u = 0; u < 64; u += 8) {
                float4 r[8];
                #pragma unroll
                for (int v = 0; v < 8; v++)
                    r[v] = __ldcs(&src[base + (size_t)(u+v)*32]);
                #pragma unroll
                for (int v = 0; v < 8; v++)
                    __stcs(&dst[base + (size_t)(u+v)*32], r[v]);
            }
        }
    }
}

// ---------------------------------------------------------------------------
// Kernel 2: blocks [0,512) run one 8-row attention tile (4 CTAs/SM), then
// ALL warps work-steal the remaining copy chunks. Last block out resets
// counters for deterministic graph replay.
// ---------------------------------------------------------------------------
__global__ __launch_bounds__(256) void fused_kernel(
    const int* __restrict__ mask, float* __restrict__ out,
    const float* __restrict__ e)
{
    extern __shared__ float sm[];
    const int t = threadIdx.x;

    if (blockIdx.x < ATTN_BLOCKS) {
        float* Qs  = sm;                  // 512  (8 x 64; later PV scratch)
        float* KsT = sm + 512;            // 8192 (K: 64k x 128j / V: 128j x 64d)
        float* S   = sm + 8704;           // 4096 (8 x 512)
        float* Mj  = sm + 12800;          // 512

        const int b  = blockIdx.x >> 6;          // 64 blocks per batch
        const int i0 = (blockIdx.x & 63) * 8;

        for (int j = t; j < NN; j += 256) Mj[j] = (float)mask[b*NN + j];
        {
            const float4* q4 = reinterpret_cast<const float4*>(g_Q + (size_t)(b*NN + i0)*DH);
            if (t < 128) reinterpret_cast<float4*>(Qs)[t] = q4[t];   // 8x64 = 128 float4
        }
        __syncthreads();

        const int tx = t & 31;            // j group (4 consecutive j)
        const int ty = t >> 5;            // row 0..7 (one row per warp)
        float4* Qs4  = reinterpret_cast<float4*>(Qs);
        float4* KsT4 = reinterpret_cast<float4*>(KsT);
        float4* S4   = reinterpret_cast<float4*>(S);

        // ---- scores over 4 j-tiles of 128 ----
        for (int jt = 0; jt < 4; jt++) {
            const int j0 = jt * 128;
            {
                const int j    = t & 127;
                const int half = t >> 7;
                const float4* K4 = reinterpret_cast<const float4*>(g_K) +
                                   (size_t)(b*NN + j0 + j) * 16;
                #pragma unroll
                for (int i2 = 0; i2 < 8; i2++) {
                    int k4 = half*8 + i2;
                    float4 v = K4[k4];
                    KsT[(k4*4+0)*128 + j] = v.x;
                    KsT[(k4*4+1)*128 + j] = v.y;
                    KsT[(k4*4+2)*128 + j] = v.z;
                    KsT[(k4*4+3)*128 + j] = v.w;
                }
            }
            __syncthreads();

            float acc0 = 0.f, acc1 = 0.f, acc2 = 0.f, acc3 = 0.f;

            #pragma unroll 4
            for (int k4 = 0; k4 < 16; k4++) {
                float4 q0 = Qs4[ty*16 + k4];           // warp-broadcast
                #pragma unroll
                for (int kk = 0; kk < 4; kk++) {
                    float4 kv = KsT4[(k4*4 + kk)*32 + tx];
                    float qa = reinterpret_cast<const float*>(&q0)[kk];
                    acc0 = fmaf(qa, kv.x, acc0);
                    acc1 = fmaf(qa, kv.y, acc1);
                    acc2 = fmaf(qa, kv.z, acc2);
                    acc3 = fmaf(qa, kv.w, acc3);
                }
            }

            {
                const float mi = Mj[i0 + ty];
                const int jb = j0 + tx*4;
                float4 s0;
                s0.x = (mi*Mj[jb+0] != 0.f) ? acc0*0.125f : -1.0e9f;
                s0.y = (mi*Mj[jb+1] != 0.f) ? acc1*0.125f : -1.0e9f;
                s0.z = (mi*Mj[jb+2] != 0.f) ? acc2*0.125f : -1.0e9f;
                s0.w = (mi*Mj[jb+3] != 0.f) ? acc3*0.125f : -1.0e9f;
                S4[ty*128 + (jb>>2)] = s0;
            }
            __syncthreads();
        }

        // ---- softmax: one row per warp ----
        {
            const int warp = t >> 5, lane = t & 31;
            const int row = warp;
            float vals[16];
            float mx = -3.4e38f;
            #pragma unroll
            for (int m = 0; m < 16; m++) {
                vals[m] = S[row*NN + lane + 32*m];
                mx = fmaxf(mx, vals[m]);
            }
            #pragma unroll
            for (int o = 16; o > 0; o >>= 1)
                mx = fmaxf(mx, __shfl_xor_sync(0xffffffffu, mx, o));
            float sum = 0.f;
            #pragma unroll
            for (int m = 0; m < 16; m++) { vals[m] = __expf(vals[m] - mx); sum += vals[m]; }
            #pragma unroll
            for (int o = 16; o > 0; o >>= 1)
                sum += __shfl_xor_sync(0xffffffffu, sum, o);
            float inv = 1.f / sum;
            #pragma unroll
            for (int m = 0; m < 16; m++) S[row*NN + lane + 32*m] = vals[m]*inv;
        }
        __syncthreads();

        // ---- out = P @ V: V staged per jt; j split by half-warp parity ----
        {
            const int row    = t >> 5;        // 0..7
            const int par    = (t >> 4) & 1;  // j-half within tile
            const int dgroup = t & 15;        // d float4 group
            float4 acc = {0.f, 0.f, 0.f, 0.f};
            float4* Vs4 = reinterpret_cast<float4*>(KsT);
            const float4* __restrict__ V4 =
                reinterpret_cast<const float4*>(g_V) + (size_t)b*NN*16;

            for (int jt = 0; jt < 4; jt++) {
                const int j0 = jt * 128;
                #pragma unroll
                for (int i2 = 0; i2 < 8; i2++) {
                    int idx = t + i2*256;
                    int r = idx >> 4, c4 = idx & 15;
                    Vs4[r*16 + c4] = V4[(size_t)(j0 + r)*16 + c4];
                }
                __syncthreads();

                #pragma unroll 4
                for (int j4 = 0; j4 < 16; j4++) {
                    float4 s  = S4[row*128 + jt*32 + par*16 + j4];
                    int jb = par*64 + j4*4;
                    float4 v0 = Vs4[(jb+0)*16 + dgroup];
                    float4 v1 = Vs4[(jb+1)*16 + dgroup];
                    float4 v2 = Vs4[(jb+2)*16 + dgroup];
                    float4 v3 = Vs4[(jb+3)*16 + dgroup];
                    acc.x = fmaf(s.x, v0.x, acc.x); acc.y = fmaf(s.x, v0.y, acc.y);
                    acc.z = fmaf(s.x, v0.z, acc.z); acc.w = fmaf(s.x, v0.w, acc.w);
                    acc.x = fmaf(s.y, v1.x, acc.x); acc.y = fmaf(s.y, v1.y, acc.y);
                    acc.z = fmaf(s.y, v1.z, acc.z); acc.w = fmaf(s.y, v1.w, acc.w);
                    acc.x = fmaf(s.z, v2.x, acc.x); acc.y = fmaf(s.z, v2.y, acc.y);
                    acc.z = fmaf(s.z, v2.z, acc.z); acc.w = fmaf(s.z, v2.w, acc.w);
                    acc.x = fmaf(s.w, v3.x, acc.x); acc.y = fmaf(s.w, v3.y, acc.y);
                    acc.z = fmaf(s.w, v3.z, acc.z); acc.w = fmaf(s.w, v3.w, acc.w);
                }
                __syncthreads();
            }

            // combine the two j-halves through scratch (reuse Qs)
            float4* Ps = reinterpret_cast<float4*>(Qs);
            if (par == 0) Ps[row*16 + dgroup] = acc;
            __syncthreads();
            if (par == 1) {
                float4 p = Ps[row*16 + dgroup];
                float m = Mj[i0 + row];
                p.x = (p.x + acc.x) * m;
                p.y = (p.y + acc.y) * m;
                p.z = (p.z + acc.z) * m;
                p.w = (p.w + acc.w) * m;
                reinterpret_cast<float4*>(out)[(size_t)(b*NN + i0 + row)*16 + dgroup] = p;
            }
        }
        __syncthreads();
    }

    // -------- copy phase: every warp work-steals remaining 32KB chunks --------
    {
        const int lane = t & 31;
        const float4* __restrict__ src = reinterpret_cast<const float4*>(e);
        float4* __restrict__ dst = reinterpret_cast<float4*>(out + (size_t)NROWS*DH);

        for (;;) {
            int c = 0;
            if (lane == 0) c = atomicAdd(&g_chunk, 1);
            c = __shfl_sync(0xffffffffu, c, 0);
            if (c >= NCHUNKS) break;

            const size_t base = (size_t)c * CHUNK4 + lane;
            #pragma unroll 1
            for (int u = 0; u < 64; u += 8) {
                float4 r[8];
                #pragma unroll
                for (int v = 0; v < 8; v++)
                    r[v] = __ldcs(&src[base + (size_t)(u+v)*32]);
                #pragma unroll
                for (int v = 0; v < 8; v++)
                    __stcs(&dst[base + (size_t)(u+v)*32], r[v]);
            }
        }
    }

    // -------- replay-safe reset by the last block out --------
    __syncthreads();
    if (t == 0) {
        int ex = atomicAdd(&g_exit, 1);
        if (ex == GRID2 - 1) {
            g_chunk = 0;
            g_done  = 0;
            g_exit  = 0;
            __threadfence();
        }
    }
}

// ---------------------------------------------------------------------------
extern "C" void kernel_launch(void* const* d_in, const int* in_sizes, int n_in,
                              void* d_out, int out_size)
{
    const float* x  = (const float*)d_in[0];
    const float* e  = (const float*)d_in[1];
    const int*  msk = (const int*)  d_in[2];
    const float* Wq = (const float*)d_in[3];
    const float* bq = (const float*)d_in[4];
    const float* Wk = (const float*)d_in[5];
    const float* bk = (const float*)d_in[6];
    const float* Wv = (const float*)d_in[7];
    const float* bv = (const float*)d_in[8];
    float* out = (float*)d_out;

    qkv_copy_kernel<<<GRID1, 256>>>(x, msk, Wq, bq, Wk, bk, Wv, bv, out, e);

    cudaFuncSetAttribute(fused_kernel, cudaFuncAttributeMaxDynamicSharedMemorySize,
                         SMEM_BYTES2);
    fused_kernel<<<GRID2, 256, SMEM_BYTES2>>>(msk, out, e);
}

// round 16
// speedup vs baseline: 1.3367x; 1.3367x over previous
#include <cuda_runtime.h>

#define NB 8
#define NN 512
#define DD 256
#define DH 64
#define NROWS (NB*NN)   // 4096

#define QKV_BLOCKS 256           // 16 rows per block (kernel 1)
#define GRID1 444

#define ATTN_BLOCKS 128          // 32 q-rows per block (kernel 2)
#define GRID2 296                // 2 CTAs/SM * 148 SMs, single wave

// e passthrough: 16777216 float4 total; 32KB chunks stolen per-warp
#define CHUNK4    2048
#define NCHUNKS   8192

// kernel2 smem: Qs 2048 + KsT 8192 + Vs 8192 + S 32*136 + Mj 512 = 23296 floats
#define SMEM_FLOATS2 23296
#define SMEM_BYTES2 (SMEM_FLOATS2 * 4)

__device__ float g_Q[NROWS*DH];
__device__ float g_K[NROWS*DH];
__device__ float g_V[NROWS*DH];
__device__ int   g_chunk;        // copy work-stealing counter (persists across kernels)
__device__ int   g_done;         // qkv completion counter
__device__ int   g_exit;         // exit counter (replay-safe reset)

// ---------------------------------------------------------------------------
// Kernel 1: blocks [0,256) project 16 rows each of Q/K/V; blocks [256,444)
// work-steal copy chunks until qkv is done, then exit (kernel 2 continues).
// ---------------------------------------------------------------------------
__global__ __launch_bounds__(256) void qkv_copy_kernel(
    const float* __restrict__ x, const int* __restrict__ mask,
    const float* __restrict__ Wq, const float* __restrict__ bq,
    const float* __restrict__ Wk, const float* __restrict__ bk,
    const float* __restrict__ Wv, const float* __restrict__ bv,
    float* __restrict__ out, const float* __restrict__ e)
{
    const int t = threadIdx.x;

    if (blockIdx.x < QKV_BLOCKS) {
        __shared__ float xs[16*DD];
        const int row0 = blockIdx.x * 16;

        const float4* x4 = reinterpret_cast<const float4*>(x + (size_t)row0 * DD);
        float4* xs4 = reinterpret_cast<float4*>(xs);
        #pragma unroll
        for (int i = t; i < 16*DD/4; i += 256) xs4[i] = x4[i];
        __syncthreads();

        const int tx = t & 63;
        const int ty = t >> 6;

        float accq[4], acck[4], accv[4];
        #pragma unroll
        for (int r = 0; r < 4; r++) { accq[r] = 0.f; acck[r] = 0.f; accv[r] = 0.f; }

        for (int k = 0; k < DD; k += 4) {
            float4 xv4[4];
            #pragma unroll
            for (int r = 0; r < 4; r++)
                xv4[r] = *reinterpret_cast<const float4*>(&xs[(ty + r*4)*DD + k]);
            #pragma unroll
            for (int kk = 0; kk < 4; kk++) {
                float wq = Wq[(k+kk)*DH + tx];
                float wk = Wk[(k+kk)*DH + tx];
                float wv = Wv[(k+kk)*DH + tx];
                #pragma unroll
                for (int r = 0; r < 4; r++) {
                    float xv = reinterpret_cast<const float*>(&xv4[r])[kk];
                    accq[r] = fmaf(xv, wq, accq[r]);
                    acck[r] = fmaf(xv, wk, acck[r]);
                    accv[r] = fmaf(xv, wv, accv[r]);
                }
            }
        }

        const float bqv = bq[tx], bkv = bk[tx], bvv = bv[tx];
        #pragma unroll
        for (int r = 0; r < 4; r++) {
            int row = row0 + ty + r*4;
            float m = (float)mask[row];
            g_Q[row*DH + tx] = (accq[r] + bqv) * m;
            g_K[row*DH + tx] = (acck[r] + bkv) * m;
            g_V[row*DH + tx] = (accv[r] + bvv) * m;
        }

        __threadfence();
        __syncthreads();
        if (t == 0) atomicAdd(&g_done, 1);
        return;
    }

    // copy blocks: steal chunks until qkv done (or exhausted)
    {
        const int lane = t & 31;
        const float4* __restrict__ src = reinterpret_cast<const float4*>(e);
        float4* __restrict__ dst = reinterpret_cast<float4*>(out + (size_t)NROWS*DH);
        volatile int* vd = &g_done;

        for (;;) {
            if (*vd >= QKV_BLOCKS) break;

            int c = 0;
            if (lane == 0) c = atomicAdd(&g_chunk, 1);
            c = __shfl_sync(0xffffffffu, c, 0);
            if (c >= NCHUNKS) break;

            const size_t base = (size_t)c * CHUNK4 + lane;
            #pragma unroll 1
            for (int u = 0; u < 64; u += 8) {
                float4 r[8];
                #pragma unroll
                for (int v = 0; v < 8; v++)
                    r[v] = __ldcs(&src[base + (size_t)(u+v)*32]);
                #pragma unroll
                for (int v = 0; v < 8; v++)
                    __stcs(&dst[base + (size_t)(u+v)*32], r[v]);
            }
        }
    }
}

// ---------------------------------------------------------------------------
// Kernel 2: blocks [0,128) = one 32-row attention tile each, flash-style
// online softmax over 4 j-tiles of 128, 4x4 register tiling (1-2 B LDS/FMA).
// Then ALL warps work-steal remaining copy chunks.
// ---------------------------------------------------------------------------
__global__ __launch_bounds__(256) void fused_kernel(
    const int* __restrict__ mask, float* __restrict__ out,
    const float* __restrict__ e)
{
    extern __shared__ float sm[];
    const int t = threadIdx.x;

    if (blockIdx.x < ATTN_BLOCKS) {
        float* Qs  = sm;                  // 2048  (32 x 64)
        float* KsT = sm + 2048;           // 8192  (64 k x 128 j)
        float* Vs  = sm + 10240;          // 8192  (128 j x 64 d)
        float* S   = sm + 18432;          // 4352  (32 x 136, padded)
        float* Mj  = sm + 22784;          // 512

        const int b  = blockIdx.x >> 4;          // 16 blocks per batch
        const int i0 = (blockIdx.x & 15) * 32;

        for (int j = t; j < NN; j += 256) Mj[j] = (float)mask[b*NN + j];
        {
            const float4* q4 = reinterpret_cast<const float4*>(g_Q + (size_t)(b*NN + i0)*DH);
            float4* qs4 = reinterpret_cast<float4*>(Qs);
            qs4[t]       = q4[t];
            qs4[t + 256] = q4[t + 256];
        }
        __syncthreads();

        const int lane = t & 31;
        const int r0   = (t >> 5) * 4;       // 4 rows per warp
        const int jc   = lane * 4;           // 4 j per lane (score phase)
        const int par  = (lane >> 4) & 1;    // PV j-half
        const int dg   = lane & 15;          // PV d float4 group

        float4* Qs4  = reinterpret_cast<float4*>(Qs);
        float4* KsT4 = reinterpret_cast<float4*>(KsT);
        float4* Vs4  = reinterpret_cast<float4*>(Vs);

        float mrow[4], lrow[4], acc[4][4];
        #pragma unroll
        for (int rr = 0; rr < 4; rr++) {
            mrow[rr] = -1.0e30f; lrow[rr] = 0.f;
            #pragma unroll
            for (int dd = 0; dd < 4; dd++) acc[rr][dd] = 0.f;
        }
        float mir[4];
        #pragma unroll
        for (int rr = 0; rr < 4; rr++) mir[rr] = Mj[i0 + r0 + rr];

        for (int jt = 0; jt < 4; jt++) {
            const int j0 = jt * 128;

            // ---- stage K (transposed) and V tiles ----
            {
                const int j    = t & 127;
                const int half = t >> 7;
                const float4* K4 = reinterpret_cast<const float4*>(g_K) +
                                   (size_t)(b*NN + j0 + j) * 16;
                #pragma unroll
                for (int i2 = 0; i2 < 8; i2++) {
                    int k4 = half*8 + i2;
                    float4 v = K4[k4];
                    KsT[(k4*4+0)*128 + j] = v.x;
                    KsT[(k4*4+1)*128 + j] = v.y;
                    KsT[(k4*4+2)*128 + j] = v.z;
                    KsT[(k4*4+3)*128 + j] = v.w;
                }
                const float4* V4 = reinterpret_cast<const float4*>(g_V) + (size_t)b*NN*16;
                #pragma unroll
                for (int i2 = 0; i2 < 8; i2++) {
                    int idx = t + i2*256;
                    int r = idx >> 4, c4 = idx & 15;
                    Vs4[r*16 + c4] = V4[(size_t)(j0 + r)*16 + c4];
                }
            }
            __syncthreads();

            // ---- scores: 4 rows x 4 j per thread ----
            float s[4][4];
            #pragma unroll
            for (int rr = 0; rr < 4; rr++)
                #pragma unroll
                for (int jj = 0; jj < 4; jj++) s[rr][jj] = 0.f;

            #pragma unroll 4
            for (int k4 = 0; k4 < 16; k4++) {
                float4 q[4];
                #pragma unroll
                for (int rr = 0; rr < 4; rr++)
                    q[rr] = Qs4[(r0+rr)*16 + k4];        // warp-broadcast
                #pragma unroll
                for (int kk = 0; kk < 4; kk++) {
                    float4 kv = KsT4[(k4*4 + kk)*32 + lane];
                    #pragma unroll
                    for (int rr = 0; rr < 4; rr++) {
                        float qa = reinterpret_cast<const float*>(&q[rr])[kk];
                        s[rr][0] = fmaf(qa, kv.x, s[rr][0]);
                        s[rr][1] = fmaf(qa, kv.y, s[rr][1]);
                        s[rr][2] = fmaf(qa, kv.z, s[rr][2]);
                        s[rr][3] = fmaf(qa, kv.w, s[rr][3]);
                    }
                }
            }

            // ---- mask + online softmax update (per row, warp-collective) ----
            float mjv[4];
            #pragma unroll
            for (int jj = 0; jj < 4; jj++) mjv[jj] = Mj[j0 + jc + jj];

            #pragma unroll
            for (int rr = 0; rr < 4; rr++) {
                #pragma unroll
                for (int jj = 0; jj < 4; jj++)
                    s[rr][jj] = (mir[rr]*mjv[jj] != 0.f) ? s[rr][jj]*0.125f : -1.0e9f;

                float tm = fmaxf(fmaxf(s[rr][0], s[rr][1]), fmaxf(s[rr][2], s[rr][3]));
                #pragma unroll
                for (int o = 16; o > 0; o >>= 1)
                    tm = fmaxf(tm, __shfl_xor_sync(0xffffffffu, tm, o));

                float mn = fmaxf(mrow[rr], tm);
                float sc = __expf(mrow[rr] - mn);
                mrow[rr] = mn;

                float sum = 0.f;
                #pragma unroll
                for (int jj = 0; jj < 4; jj++) {
                    float p = __expf(s[rr][jj] - mn);
                    s[rr][jj] = p;
                    sum += p;
                }
                #pragma unroll
                for (int o = 16; o > 0; o >>= 1)
                    sum += __shfl_xor_sync(0xffffffffu, sum, o);

                lrow[rr] = lrow[rr]*sc + sum;
                #pragma unroll
                for (int dd = 0; dd < 4; dd++) acc[rr][dd] *= sc;

                *reinterpret_cast<float4*>(&S[(r0+rr)*136 + jc]) =
                    make_float4(s[rr][0], s[rr][1], s[rr][2], s[rr][3]);
            }
            __syncthreads();

            // ---- PV accumulate: 4 rows x 4 d per thread, half of j ----
            #pragma unroll 4
            for (int jl = 0; jl < 64; jl++) {
                const int j = par*64 + jl;
                float4 v = Vs4[j*16 + dg];
                #pragma unroll
                for (int rr = 0; rr < 4; rr++) {
                    float p = S[(r0+rr)*136 + j];
                    acc[rr][0] = fmaf(p, v.x, acc[rr][0]);
                    acc[rr][1] = fmaf(p, v.y, acc[rr][1]);
                    acc[rr][2] = fmaf(p, v.z, acc[rr][2]);
                    acc[rr][3] = fmaf(p, v.w, acc[rr][3]);
                }
            }
            __syncthreads();    // before next tile overwrites KsT/Vs
        }

        // ---- combine j-halves (via smem scratch) and write out ----
        {
            float4* Ps = reinterpret_cast<float4*>(KsT);   // 32x16 float4 scratch
            if (par == 0) {
                #pragma unroll
                for (int rr = 0; rr < 4; rr++)
                    Ps[(r0+rr)*16 + dg] = make_float4(acc[rr][0], acc[rr][1],
                                                      acc[rr][2], acc[rr][3]);
            }
            __syncthreads();
            if (par == 1) {
                #pragma unroll
                for (int rr = 0; rr < 4; rr++) {
                    float4 p = Ps[(r0+rr)*16 + dg];
                    float inv = mir[rr] / lrow[rr];
                    p.x = (p.x + acc[rr][0]) * inv;
                    p.y = (p.y + acc[rr][1]) * inv;
                    p.z = (p.z + acc[rr][2]) * inv;
                    p.w = (p.w + acc[rr][3]) * inv;
                    reinterpret_cast<float4*>(out)[(size_t)(b*NN + i0 + r0 + rr)*16 + dg] = p;
                }
            }
        }
        __syncthreads();
    }

    // -------- copy phase: every warp work-steals remaining 32KB chunks --------
    {
        const int lane = t & 31;
        const float4* __restrict__ src = reinterpret_cast<const float4*>(e);
        float4* __restrict__ dst = reinterpret_cast<float4*>(out + (size_t)NROWS*DH);

        for (;;) {
            int c = 0;
            if (lane == 0) c = atomicAdd(&g_chunk, 1);
            c = __shfl_sync(0xffffffffu, c, 0);
            if (c >= NCHUNKS) break;

            const size_t base = (size_t)c * CHUNK4 + lane;
            #pragma unroll 1
            for (int u = 0; u < 64; u += 8) {
                float4 r[8];
                #pragma unroll
                for (int v = 0; v < 8; v++)
                    r[v] = __ldcs(&src[base + (size_t)(u+v)*32]);
                #pragma unroll
                for (int v = 0; v < 8; v++)
                    __stcs(&dst[base + (size_t)(u+v)*32], r[v]);
            }
        }
    }

    // -------- replay-safe reset by the last block out --------
    __syncthreads();
    if (t == 0) {
        int ex = atomicAdd(&g_exit, 1);
        if (ex == GRID2 - 1) {
            g_chunk = 0;
            g_done  = 0;
            g_exit  = 0;
            __threadfence();
        }
    }
}

// ---------------------------------------------------------------------------
extern "C" void kernel_launch(void* const* d_in, const int* in_sizes, int n_in,
                              void* d_out, int out_size)
{
    const float* x  = (const float*)d_in[0];
    const float* e  = (const float*)d_in[1];
    const int*  msk = (const int*)  d_in[2];
    const float* Wq = (const float*)d_in[3];
    const float* bq = (const float*)d_in[4];
    const float* Wk = (const float*)d_in[5];
    const float* bk = (const float*)d_in[6];
    const float* Wv = (const float*)d_in[7];
    const float* bv = (const float*)d_in[8];
    float* out = (float*)d_out;

    qkv_copy_kernel<<<GRID1, 256>>>(x, msk, Wq, bq, Wk, bk, Wv, bv, out, e);

    cudaFuncSetAttribute(fused_kernel, cudaFuncAttributeMaxDynamicSharedMemorySize,
                         SMEM_BYTES2);
    fused_kernel<<<GRID2, 256, SMEM_BYTES2>>>(msk, out, e);
}